// round 16
// baseline (speedup 1.0000x reference)
#include <cuda_runtime.h>
#include <cuda_bf16.h>
#include <cuda_fp16.h>

// Problem constants
#define NN      20000        // nodes
#define NE      320000       // raw edges
#define NET     340000       // edges + self loops
#define IN_CH   256
#define HID     128
#define HEADS   4
#define F1      (HEADS*HID)  // 512
#define NG      128          // graphs
#define OC      16
#define NEG     0.2f

#define RB_ALL  ((NN + 127) / 128)          // 157 row blocks

// ------------------------- device scratch -------------------------
__device__ __align__(16) __half g_xh  [NN * IN_CH];   // x in fp16
__device__ __align__(16) __half g_w1t [F1 * IN_CH];   // W1^T [n][k] fp16
__device__ __align__(16) __half g_w2t [HID * F1];     // W2^T [n][k] fp16
__device__ __align__(16) __half g_h1h [NN * F1];      // x @ W1 (fp16)
__device__ __align__(16) __half g_h1bh[NN * F1];      // relu(agg1 + b1) (fp16)
__device__ __align__(16) __half g_h2h [NN * HID];     // h1b @ W2 (fp16)
__device__ float  g_as1 [NN * HEADS];
__device__ float  g_ad1 [NN * HEADS];
__device__ float  g_as2 [NN];
__device__ float  g_ad2 [NN];
__device__ int    g_counts [NN];
__device__ int    g_rowstart[NN + 1];
__device__ int    g_cursor [NN];
__device__ int    g_csrsrc [NET];
__device__ float  g_pooled [NG * HID];
__device__ float  g_gcnt   [NG];
__device__ int    g_idx64;

#define SCH 1024
#define SNB ((NN + SCH - 1) / SCH)     // 20
__device__ int g_bsum[SNB];

// ------------------------- helpers -------------------------
__device__ __forceinline__ float warpSum(float v) {
    #pragma unroll
    for (int o = 16; o > 0; o >>= 1) v += __shfl_xor_sync(0xffffffffu, v, o);
    return v;
}
__device__ __forceinline__ float lrelu(float x) { return x > 0.f ? x : NEG * x; }
__device__ __forceinline__ int clampi(int v, int hi) {
    return v < 0 ? 0 : (v >= hi ? hi - 1 : v);
}
__device__ __forceinline__ int idx_at(const void* p, int i) {
    if (g_idx64) return (int)((const long long*)p)[i];
    return ((const int*)p)[i];
}
__device__ __forceinline__ void mma_f16(float* c, unsigned a0, unsigned a1,
                                        unsigned a2, unsigned a3,
                                        unsigned b0, unsigned b1) {
    asm("mma.sync.aligned.m16n8k16.row.col.f32.f16.f16.f32 "
        "{%0,%1,%2,%3}, {%4,%5,%6,%7}, {%8,%9}, {%0,%1,%2,%3};"
        : "+f"(c[0]), "+f"(c[1]), "+f"(c[2]), "+f"(c[3])
        : "r"(a0), "r"(a1), "r"(a2), "r"(a3), "r"(b0), "r"(b1));
}
__device__ __forceinline__ void cp16(void* dst, const void* src, int sz) {
    unsigned d = (unsigned)__cvta_generic_to_shared(dst);
    asm volatile("cp.async.ca.shared.global [%0], [%1], 16, %2;"
                 :: "r"(d), "l"(src), "r"(sz));
}
__device__ __forceinline__ void cp_commit() { asm volatile("cp.async.commit_group;"); }
template<int N> __device__ __forceinline__ void cp_wait() {
    asm volatile("cp.async.wait_group %0;" :: "n"(N));
}

// ------------------------- conversion kernels -------------------------
__global__ void cvt_x_kernel(const float* __restrict__ x) {
    int i4 = blockIdx.x * blockDim.x + threadIdx.x;
    if (i4 >= NN * IN_CH / 4) return;
    float4 v = ((const float4*)x)[i4];
    __half2 h01 = __floats2half2_rn(v.x, v.y);
    __half2 h23 = __floats2half2_rn(v.z, v.w);
    ((uint2*)g_xh)[i4] = make_uint2(*(unsigned*)&h01, *(unsigned*)&h23);
}
__global__ void cvt_w1_kernel(const float* __restrict__ W1) {   // [k][n] -> [n][k]
    int i = blockIdx.x * blockDim.x + threadIdx.x;
    if (i >= F1 * IN_CH) return;
    int n = i / IN_CH, k = i % IN_CH;
    g_w1t[i] = __float2half_rn(W1[k * F1 + n]);
}
__global__ void cvt_w2_kernel(const float* __restrict__ W2) {   // [k][n] -> [n][k]
    int i = blockIdx.x * blockDim.x + threadIdx.x;
    if (i >= HID * F1) return;
    int n = i / F1, k = i % F1;
    g_w2t[i] = __float2half_rn(W2[k * HID + n]);
}

// ------------------------- zero scratch + dtype detection -------------------------
// Grid MUST cover NN (g_counts) — stale counts accumulate across graph replays
// otherwise and corrupt the CSR (R8 bug).
__global__ void zero_kernel(const int* __restrict__ ei32) {
    int i = blockIdx.x * blockDim.x + threadIdx.x;
    if (i == 0) {
        int allzero = 1;
        #pragma unroll 1
        for (int k = 1; k < 128; k += 2)
            if (ei32[k] != 0) { allzero = 0; break; }
        g_idx64 = allzero;
    }
    if (i < NN) g_counts[i] = 0;
    if (i < NG * HID) g_pooled[i] = 0.f;
    if (i < NG) g_gcnt[i] = 0.f;
}

// ------------------------- CSR build -------------------------
__global__ void hist_kernel(const void* __restrict__ ei) {
    int i = blockIdx.x * blockDim.x + threadIdx.x;
    if (i >= NET) return;
    int dst = (i < NE) ? clampi(idx_at(ei, NE + i), NN) : (i - NE);
    atomicAdd(&g_counts[dst], 1);
}

__global__ void scan1_kernel() {
    __shared__ int sbuf[SCH];
    int b = blockIdx.x, t = threadIdx.x;
    int i = b * SCH + t;
    int v = (i < NN) ? g_counts[i] : 0;
    sbuf[t] = v;
    __syncthreads();
    #pragma unroll
    for (int off = 1; off < SCH; off <<= 1) {
        int x = (t >= off) ? sbuf[t - off] : 0;
        __syncthreads();
        sbuf[t] += x;
        __syncthreads();
    }
    if (i < NN) g_rowstart[i + 1] = sbuf[t];
    if (t == SCH - 1) g_bsum[b] = sbuf[t];
}

__global__ void scan3_kernel() {
    int i = blockIdx.x * blockDim.x + threadIdx.x;
    if (i >= NN) return;
    if (i == 0) g_rowstart[0] = 0;
    int blk = i >> 10;
    int off = 0;
    for (int b = 0; b < blk; b++) off += g_bsum[b];
    int fin = g_rowstart[i + 1] + off;
    g_rowstart[i + 1] = fin;
    g_cursor[i] = fin - g_counts[i];
}

__global__ void scatter_kernel(const void* __restrict__ ei) {
    int i = blockIdx.x * blockDim.x + threadIdx.x;
    if (i >= NET) return;
    int src, dst;
    if (i < NE) {
        src = clampi(idx_at(ei, i), NN);
        dst = clampi(idx_at(ei, NE + i), NN);
    } else {
        src = dst = i - NE;
    }
    int pos = atomicAdd(&g_cursor[dst], 1);
    g_csrsrc[pos] = src;
}

// ------------------------- FP16 GEMM 128x128, 2-stage cp.async, fused att ------
// C[M,N] = A[M,K] @ Bt[N,K]^T, fp32 accum -> half. colOff shifts the N block
// (per-head launches for gemm1 pipelining).
#define GBM 128
#define GBN 128
#define HK  32
#define HPAD 8

__device__ __forceinline__ void f16_gemm_fused(const __half* __restrict__ A,
                                               const __half* __restrict__ Bt,
                                               __half* __restrict__ Ch,
                                               int M, int N, int K,
                                               const float* __restrict__ attS,
                                               const float* __restrict__ attD,
                                               float* __restrict__ asOut,
                                               float* __restrict__ adOut,
                                               int heads, int colOff) {
    __shared__ __half As[2][GBM][HK + HPAD];
    __shared__ __half Bs[2][GBN][HK + HPAD];
    __shared__ float s_eas[2][GBM];
    __shared__ float s_ead[2][GBM];

    int tid  = threadIdx.x;
    int lane = tid & 31;
    int warp = tid >> 5;
    int wm = warp & 3;
    int wn = warp >> 2;
    int rowBase = blockIdx.y * GBM;
    int colBase = (blockIdx.x + colOff) * GBN;
    int q  = lane & 3;
    int r0 = lane >> 2;

    int ldRow = tid >> 2;
    int ldCol = (tid & 3) * 8;

    int nIter = K / HK;
    float acc[2][8][4] = {};

    {
        #pragma unroll
        for (int i = 0; i < 2; i++) {
            int row = ldRow + 64 * i;
            int gr = rowBase + row;
            const __half* src = (gr < M) ? &A[(long long)gr * K + ldCol] : A;
            cp16(&As[0][row][ldCol], src, (gr < M) ? 16 : 0);
            cp16(&Bs[0][row][ldCol], &Bt[(long long)(colBase + row) * K + ldCol], 16);
        }
        cp_commit();
    }

    for (int it = 0; it < nIter; it++) {
        int cur = it & 1;
        cp_wait<0>();
        __syncthreads();

        if (it + 1 < nIter) {
            int k0 = (it + 1) * HK;
            int st = cur ^ 1;
            #pragma unroll
            for (int i = 0; i < 2; i++) {
                int row = ldRow + 64 * i;
                int gr = rowBase + row;
                const __half* src = (gr < M) ? &A[(long long)gr * K + k0 + ldCol] : A;
                cp16(&As[st][row][ldCol], src, (gr < M) ? 16 : 0);
                cp16(&Bs[st][row][ldCol], &Bt[(long long)(colBase + row) * K + k0 + ldCol], 16);
            }
            cp_commit();
        }

        #pragma unroll
        for (int kk = 0; kk < 2; kk++) {
            int kb = kk * 16;
            unsigned a[2][4], b[8][2];
            #pragma unroll
            for (int mf = 0; mf < 2; mf++) {
                int mrow = wm * 32 + mf * 16 + r0;
                a[mf][0] = *(const unsigned*)&As[cur][mrow    ][kb + 2*q    ];
                a[mf][1] = *(const unsigned*)&As[cur][mrow + 8][kb + 2*q    ];
                a[mf][2] = *(const unsigned*)&As[cur][mrow    ][kb + 2*q + 8];
                a[mf][3] = *(const unsigned*)&As[cur][mrow + 8][kb + 2*q + 8];
            }
            #pragma unroll
            for (int nf = 0; nf < 8; nf++) {
                int ncol = wn * 64 + nf * 8 + r0;
                b[nf][0] = *(const unsigned*)&Bs[cur][ncol][kb + 2*q    ];
                b[nf][1] = *(const unsigned*)&Bs[cur][ncol][kb + 2*q + 8];
            }
            #pragma unroll
            for (int mf = 0; mf < 2; mf++)
                #pragma unroll
                for (int nf = 0; nf < 8; nf++)
                    mma_f16(acc[mf][nf], a[mf][0], a[mf][1], a[mf][2], a[mf][3],
                            b[nf][0], b[nf][1]);
        }
        __syncthreads();
    }

    int hd = colBase / HID;
    float attSv[16], attDv[16];
    #pragma unroll
    for (int nf = 0; nf < 8; nf++) {
        int gc = colBase + wn * 64 + nf * 8 + 2 * q;
        attSv[nf*2]   = attS[gc];   attSv[nf*2+1] = attS[gc+1];
        attDv[nf*2]   = attD[gc];   attDv[nf*2+1] = attD[gc+1];
    }
    #pragma unroll
    for (int mf = 0; mf < 2; mf++) {
        int rT = wm * 32 + mf * 16 + r0;
        float psT = 0.f, pdT = 0.f, psB = 0.f, pdB = 0.f;
        #pragma unroll
        for (int nf = 0; nf < 8; nf++) {
            psT += acc[mf][nf][0]*attSv[nf*2] + acc[mf][nf][1]*attSv[nf*2+1];
            pdT += acc[mf][nf][0]*attDv[nf*2] + acc[mf][nf][1]*attDv[nf*2+1];
            psB += acc[mf][nf][2]*attSv[nf*2] + acc[mf][nf][3]*attSv[nf*2+1];
            pdB += acc[mf][nf][2]*attDv[nf*2] + acc[mf][nf][3]*attDv[nf*2+1];
        }
        #pragma unroll
        for (int o = 1; o < 4; o <<= 1) {
            psT += __shfl_xor_sync(0xffffffffu, psT, o);
            pdT += __shfl_xor_sync(0xffffffffu, pdT, o);
            psB += __shfl_xor_sync(0xffffffffu, psB, o);
            pdB += __shfl_xor_sync(0xffffffffu, pdB, o);
        }
        if (q == 0) {
            s_eas[wn][rT]     = psT;  s_ead[wn][rT]     = pdT;
            s_eas[wn][rT + 8] = psB;  s_ead[wn][rT + 8] = pdB;
        }
        #pragma unroll
        for (int nf = 0; nf < 8; nf++) {
            int gc = colBase + wn * 64 + nf * 8 + 2 * q;
            int gr0 = rowBase + rT;
            if (gr0 < M)
                *(__half2*)&Ch[(long long)gr0 * N + gc] =
                    __floats2half2_rn(acc[mf][nf][0], acc[mf][nf][1]);
            if (gr0 + 8 < M)
                *(__half2*)&Ch[(long long)(gr0 + 8) * N + gc] =
                    __floats2half2_rn(acc[mf][nf][2], acc[mf][nf][3]);
        }
    }
    __syncthreads();
    if (tid < GBM) {
        int gr = rowBase + tid;
        if (gr < M) {
            asOut[gr * heads + hd] = s_eas[0][tid] + s_eas[1][tid];
            adOut[gr * heads + hd] = s_ead[0][tid] + s_ead[1][tid];
        }
    }
}

__global__ __launch_bounds__(256) void gemm1_kernel(const float* __restrict__ as1,
                                                    const float* __restrict__ ad1,
                                                    int colOff) {
    f16_gemm_fused(g_xh, g_w1t, g_h1h, NN, F1, IN_CH, as1, ad1, g_as1, g_ad1,
                   HEADS, colOff);
}

__global__ __launch_bounds__(256) void gemm2_kernel(const float* __restrict__ as2,
                                                    const float* __restrict__ ad2) {
    f16_gemm_fused(g_h1bh, g_w2t, g_h2h, NN, HID, F1, as2, ad2, g_as2, g_ad2,
                   1, 0);
}

// ------------------------- per-head layer-1 aggregation -------------------------
// Block 128 = 2 groups x 64 threads; thread (g,c) owns cols 2c,2c+1 of head hd.
// Single pass: unnormalized accumulate + Σw, divide at end (== softmax).
__global__ __launch_bounds__(128) void agg1h_kernel(const float* __restrict__ b1,
                                                    int hd) {
    int n = blockIdx.x, t = threadIdx.x;
    int beg = g_rowstart[n], end = g_rowstart[n + 1];
    float adst = g_ad1[n * HEADS + hd];
    int grp = t >> 6;
    int c   = t & 63;

    __shared__ float s_w[64];
    __shared__ int   ssrc[64];
    __shared__ float s_accB[HID];
    __shared__ float wr2[2];

    float2 acc = make_float2(0.f, 0.f);
    float dsum = 0.f;

    for (int base = beg; base < end; base += 64) {
        int cnt = min(64, end - base);
        __syncthreads();
        if (t < cnt) {
            int s = g_csrsrc[base + t];
            ssrc[t] = s;
            float w = __expf(lrelu(g_as1[s * HEADS + hd] + adst));
            s_w[t] = w;
            dsum += w;
        }
        __syncthreads();
        for (int qq = grp; qq < cnt; qq += 2) {
            int s = ssrc[qq];
            float w = s_w[qq];
            float2 f = __half22float2(
                *(const __half2*)&g_h1h[(long long)s * F1 + hd * HID + 2 * c]);
            acc.x += w * f.x; acc.y += w * f.y;
        }
    }
    dsum = warpSum(dsum);                       // partials in warps 0,1 only
    if ((t & 31) == 0 && t < 64) wr2[t >> 5] = dsum;
    if (grp == 1) { s_accB[2 * c] = acc.x; s_accB[2 * c + 1] = acc.y; }
    __syncthreads();
    if (grp == 0) {
        float di = 1.f / (wr2[0] + wr2[1]);
        float o0 = fmaxf((acc.x + s_accB[2 * c])     * di + b1[hd * HID + 2 * c],     0.f);
        float o1 = fmaxf((acc.y + s_accB[2 * c + 1]) * di + b1[hd * HID + 2 * c + 1], 0.f);
        __half2 h = __floats2half2_rn(o0, o1);
        *(__half2*)&g_h1bh[(long long)n * F1 + hd * HID + 2 * c] = h;
    }
}

// ------------------------- layer-2 aggregation: single pass + fused pool ------
__global__ __launch_bounds__(128) void agg2_kernel(const float* __restrict__ b2,
                                                   const void* __restrict__ batch) {
    int n = blockIdx.x, t = threadIdx.x;
    int beg = g_rowstart[n], end = g_rowstart[n + 1];
    float adst = g_ad2[n];
    int grp = t >> 6;
    int c   = t & 63;

    __shared__ float s_w[64];
    __shared__ int   ssrc[64];
    __shared__ float s_accB[HID];
    __shared__ float wr2[2];

    float2 acc = make_float2(0.f, 0.f);
    float dsum = 0.f;

    for (int base = beg; base < end; base += 64) {
        int cnt = min(64, end - base);
        __syncthreads();
        if (t < cnt) {
            int s = g_csrsrc[base + t];
            ssrc[t] = s;
            float w = __expf(lrelu(g_as2[s] + adst));
            s_w[t] = w;
            dsum += w;
        }
        __syncthreads();
        for (int qq = grp; qq < cnt; qq += 2) {
            int s = ssrc[qq];
            float w = s_w[qq];
            float2 f = __half22float2(*(const __half2*)&g_h2h[(long long)s * HID + 2 * c]);
            acc.x += w * f.x; acc.y += w * f.y;
        }
    }
    dsum = warpSum(dsum);
    if ((t & 31) == 0 && t < 64) wr2[t >> 5] = dsum;
    if (grp == 1) { s_accB[2 * c] = acc.x; s_accB[2 * c + 1] = acc.y; }
    __syncthreads();
    if (grp == 0) {
        float di = 1.f / (wr2[0] + wr2[1]);
        float o0 = (acc.x + s_accB[2 * c])     * di + b2[2 * c];
        float o1 = (acc.y + s_accB[2 * c + 1]) * di + b2[2 * c + 1];
        int g = clampi(idx_at(batch, n), NG);
        atomicAdd(&g_pooled[g * HID + 2 * c],     o0);
        atomicAdd(&g_pooled[g * HID + 2 * c + 1], o1);
        if (t == 0) atomicAdd(&g_gcnt[g], 1.0f);
    }
}

// ------------------------- MLP head -------------------------
__global__ void mlp_kernel(const float* __restrict__ Wm1, const float* __restrict__ bm1,
                           const float* __restrict__ Wm2, const float* __restrict__ bm2,
                           float* __restrict__ out) {
    int g = blockIdx.x, t = threadIdx.x;
    __shared__ float p[HID], z[HID];
    float c = fmaxf(g_gcnt[g], 1.0f);
    p[t] = g_pooled[g * HID + t] / c;
    __syncthreads();
    float a = bm1[t];
    #pragma unroll 8
    for (int k = 0; k < HID; k++) a += p[k] * Wm1[k * HID + t];
    z[t] = a > 0.f ? a : 0.f;
    __syncthreads();
    if (t < OC) {
        float o = bm2[t];
        #pragma unroll 8
        for (int k = 0; k < HID; k++) o += z[k] * Wm2[k * OC + t];
        out[g * OC + t] = o;
    }
}

// ------------------------- launch -------------------------
// DAG:
//   s2: cvt_x, cvt_w1, gemm1 head 0..3 (event per head)
//   s0: cvt_w2 + CSR chain, then per head h: wait(eH[h]) -> agg1h(h)
//   s0: gemm2 (all heads of h1bh ready on s0) -> agg2 -> mlp
// gemm1 col-block h produces exactly head-h columns + head-h att logits, so
// agg1h(h) only needs eH[h]. gemm1 (tensor-bound) overlaps agg1h (L2-bound).
// Streams/events created fresh per call, never destroyed (graph-capture safe).
extern "C" void kernel_launch(void* const* d_in, const int* in_sizes, int n_in,
                              void* d_out, int out_size) {
    const float* x    = (const float*)d_in[0];
    const void*  ei   = d_in[1];
    const void*  bat  = d_in[2];
    const float* W1   = (const float*)d_in[3];
    const float* as1  = (const float*)d_in[4];
    const float* ad1  = (const float*)d_in[5];
    const float* b1   = (const float*)d_in[6];
    const float* W2   = (const float*)d_in[7];
    const float* as2  = (const float*)d_in[8];
    const float* ad2  = (const float*)d_in[9];
    const float* b2   = (const float*)d_in[10];
    const float* Wm1  = (const float*)d_in[11];
    const float* bm1  = (const float*)d_in[12];
    const float* Wm2  = (const float*)d_in[13];
    const float* bm2  = (const float*)d_in[14];
    float* out = (float*)d_out;

    cudaStream_t s2;
    cudaStreamCreateWithFlags(&s2, cudaStreamNonBlocking);
    cudaEvent_t eFork, eH[HEADS];
    cudaEventCreateWithFlags(&eFork, cudaEventDisableTiming);
    for (int h = 0; h < HEADS; h++)
        cudaEventCreateWithFlags(&eH[h], cudaEventDisableTiming);

    // fork
    cudaEventRecord(eFork, 0);
    cudaStreamWaitEvent(s2, eFork, 0);

    // s2: fp16 conversions + gemm1, one column block (= one head) at a time
    cvt_x_kernel <<<(NN * IN_CH / 4 + 255) / 256, 256, 0, s2>>>(x);
    cvt_w1_kernel<<<(F1 * IN_CH + 255) / 256, 256, 0, s2>>>(W1);
    for (int h = 0; h < HEADS; h++) {
        dim3 grid(1, RB_ALL);
        gemm1_kernel<<<grid, 256, 0, s2>>>(as1, ad1, h);
        cudaEventRecord(eH[h], s2);
    }

    // s0: W2 convert + CSR build
    cvt_w2_kernel<<<(HID * F1 + 255) / 256, 256>>>(W2);
    zero_kernel<<<(NN + 255) / 256, 256>>>((const int*)ei);   // must cover NN!
    hist_kernel<<<(NET + 255) / 256, 256>>>(ei);
    scan1_kernel<<<SNB, SCH>>>();
    scan3_kernel<<<(NN + 255) / 256, 256>>>();
    scatter_kernel<<<(NET + 255) / 256, 256>>>(ei);

    // s0: per-head aggregation, pipelined against remaining gemm1 col blocks
    for (int h = 0; h < HEADS; h++) {
        cudaStreamWaitEvent(0, eH[h], 0);
        agg1h_kernel<<<NN, 128>>>(b1, h);
    }

    // s0: layer 2 (h1bh complete on this stream)
    {
        dim3 grid(HID / GBN, RB_ALL);
        gemm2_kernel<<<grid, 256>>>(as2, ad2);
    }
    agg2_kernel<<<NN, 128>>>(b2, bat);

    mlp_kernel<<<NG, HID>>>(Wm1, bm1, Wm2, bm2, out);
}

// round 17
// speedup vs baseline: 1.4427x; 1.4427x over previous
#include <cuda_runtime.h>
#include <cuda_bf16.h>
#include <cuda_fp16.h>

// Problem constants
#define NN      20000        // nodes
#define NE      320000       // raw edges
#define NET     340000       // edges + self loops
#define IN_CH   256
#define HID     128
#define HEADS   4
#define F1      (HEADS*HID)  // 512
#define NG      128          // graphs
#define OC      16
#define NEG     0.2f

// node split for layer1->layer2 pipelining (multiple of 128)
#define NLO     10112
#define RB_ALL  ((NN + 127) / 128)          // 157 row blocks
#define RB_LO   (NLO / 128)                 // 79
#define RB_HI   (RB_ALL - RB_LO)            // 78

// ------------------------- device scratch -------------------------
__device__ __align__(16) __half g_xh  [NN * IN_CH];   // x in fp16
__device__ __align__(16) __half g_w1t [F1 * IN_CH];   // W1^T [n][k] fp16
__device__ __align__(16) __half g_w2t [HID * F1];     // W2^T [n][k] fp16
__device__ __align__(16) __half g_h1h [NN * F1];      // x @ W1 (fp16)
__device__ __align__(16) __half g_h1bh[NN * F1];      // relu(agg1 + b1) (fp16)
__device__ __align__(16) __half g_h2h [NN * HID];     // h1b @ W2 (fp16)
__device__ float  g_as1 [NN * HEADS];
__device__ float  g_ad1 [NN * HEADS];
__device__ float  g_as2 [NN];
__device__ float  g_ad2 [NN];
__device__ int    g_counts [NN];
__device__ int    g_rowstart[NN + 1];
__device__ int    g_cursor [NN];
__device__ int    g_csrsrc [NET];
__device__ float  g_pooled [NG * HID];
__device__ float  g_gcnt   [NG];
__device__ int    g_idx64;

#define SCH 1024
#define SNB ((NN + SCH - 1) / SCH)     // 20
__device__ int g_bsum[SNB];

// ------------------------- helpers -------------------------
__device__ __forceinline__ float warpSum(float v) {
    #pragma unroll
    for (int o = 16; o > 0; o >>= 1) v += __shfl_xor_sync(0xffffffffu, v, o);
    return v;
}
__device__ __forceinline__ float lrelu(float x) { return x > 0.f ? x : NEG * x; }
__device__ __forceinline__ int clampi(int v, int hi) {
    return v < 0 ? 0 : (v >= hi ? hi - 1 : v);
}
__device__ __forceinline__ int idx_at(const void* p, int i) {
    if (g_idx64) return (int)((const long long*)p)[i];
    return ((const int*)p)[i];
}
__device__ __forceinline__ void mma_f16(float* c, unsigned a0, unsigned a1,
                                        unsigned a2, unsigned a3,
                                        unsigned b0, unsigned b1) {
    asm("mma.sync.aligned.m16n8k16.row.col.f32.f16.f16.f32 "
        "{%0,%1,%2,%3}, {%4,%5,%6,%7}, {%8,%9}, {%0,%1,%2,%3};"
        : "+f"(c[0]), "+f"(c[1]), "+f"(c[2]), "+f"(c[3])
        : "r"(a0), "r"(a1), "r"(a2), "r"(a3), "r"(b0), "r"(b1));
}
__device__ __forceinline__ void cp16(void* dst, const void* src, int sz) {
    unsigned d = (unsigned)__cvta_generic_to_shared(dst);
    asm volatile("cp.async.ca.shared.global [%0], [%1], 16, %2;"
                 :: "r"(d), "l"(src), "r"(sz));
}
__device__ __forceinline__ void cp_commit() { asm volatile("cp.async.commit_group;"); }
template<int N> __device__ __forceinline__ void cp_wait() {
    asm volatile("cp.async.wait_group %0;" :: "n"(N));
}

// ------------------------- conversion kernels -------------------------
__global__ void cvt_x_kernel(const float* __restrict__ x) {
    int i4 = blockIdx.x * blockDim.x + threadIdx.x;
    if (i4 >= NN * IN_CH / 4) return;
    float4 v = ((const float4*)x)[i4];
    __half2 h01 = __floats2half2_rn(v.x, v.y);
    __half2 h23 = __floats2half2_rn(v.z, v.w);
    ((uint2*)g_xh)[i4] = make_uint2(*(unsigned*)&h01, *(unsigned*)&h23);
}
__global__ void cvt_w1_kernel(const float* __restrict__ W1) {   // [k][n] -> [n][k]
    int i = blockIdx.x * blockDim.x + threadIdx.x;
    if (i >= F1 * IN_CH) return;
    int n = i / IN_CH, k = i % IN_CH;
    g_w1t[i] = __float2half_rn(W1[k * F1 + n]);
}
__global__ void cvt_w2_kernel(const float* __restrict__ W2) {   // [k][n] -> [n][k]
    int i = blockIdx.x * blockDim.x + threadIdx.x;
    if (i >= HID * F1) return;
    int n = i / F1, k = i % F1;
    g_w2t[i] = __float2half_rn(W2[k * HID + n]);
}

// ------------------------- zero scratch + dtype detection -------------------------
// Grid MUST cover NN (g_counts) — stale counts accumulate across graph replays
// otherwise and corrupt the CSR (R8 bug).
__global__ void zero_kernel(const int* __restrict__ ei32) {
    int i = blockIdx.x * blockDim.x + threadIdx.x;
    if (i == 0) {
        int allzero = 1;
        #pragma unroll 1
        for (int k = 1; k < 128; k += 2)
            if (ei32[k] != 0) { allzero = 0; break; }
        g_idx64 = allzero;
    }
    if (i < NN) g_counts[i] = 0;
    if (i < NG * HID) g_pooled[i] = 0.f;
    if (i < NG) g_gcnt[i] = 0.f;
}

// ------------------------- CSR build -------------------------
__global__ void hist_kernel(const void* __restrict__ ei) {
    int i = blockIdx.x * blockDim.x + threadIdx.x;
    if (i >= NET) return;
    int dst = (i < NE) ? clampi(idx_at(ei, NE + i), NN) : (i - NE);
    atomicAdd(&g_counts[dst], 1);
}

__global__ void scan1_kernel() {
    __shared__ int sbuf[SCH];
    int b = blockIdx.x, t = threadIdx.x;
    int i = b * SCH + t;
    int v = (i < NN) ? g_counts[i] : 0;
    sbuf[t] = v;
    __syncthreads();
    #pragma unroll
    for (int off = 1; off < SCH; off <<= 1) {
        int x = (t >= off) ? sbuf[t - off] : 0;
        __syncthreads();
        sbuf[t] += x;
        __syncthreads();
    }
    if (i < NN) g_rowstart[i + 1] = sbuf[t];
    if (t == SCH - 1) g_bsum[b] = sbuf[t];
}

__global__ void scan3_kernel() {
    int i = blockIdx.x * blockDim.x + threadIdx.x;
    if (i >= NN) return;
    if (i == 0) g_rowstart[0] = 0;
    int blk = i >> 10;
    int off = 0;
    for (int b = 0; b < blk; b++) off += g_bsum[b];
    int fin = g_rowstart[i + 1] + off;
    g_rowstart[i + 1] = fin;
    g_cursor[i] = fin - g_counts[i];
}

__global__ void scatter_kernel(const void* __restrict__ ei) {
    int i = blockIdx.x * blockDim.x + threadIdx.x;
    if (i >= NET) return;
    int src, dst;
    if (i < NE) {
        src = clampi(idx_at(ei, i), NN);
        dst = clampi(idx_at(ei, NE + i), NN);
    } else {
        src = dst = i - NE;
    }
    int pos = atomicAdd(&g_cursor[dst], 1);
    g_csrsrc[pos] = src;
}

// ------------------------- FP16 GEMM 128x128, 2-stage cp.async, fused att ------
// C[M,N] = A[M,K] @ Bt[N,K]^T, fp32 accum -> half. rowBlockOff shifts the M
// block range so halves of the row space can run on different streams.
// NOTE (R16 lesson): never split the N/column dimension into separate
// launches — each launch re-reads all of A and the reuse loss (4x A traffic,
// 15.5us/launch) dwarfs any pipeline overlap gain.
#define GBM 128
#define GBN 128
#define HK  32
#define HPAD 8

__device__ __forceinline__ void f16_gemm_fused(const __half* __restrict__ A,
                                               const __half* __restrict__ Bt,
                                               __half* __restrict__ Ch,
                                               int M, int N, int K,
                                               const float* __restrict__ attS,
                                               const float* __restrict__ attD,
                                               float* __restrict__ asOut,
                                               float* __restrict__ adOut,
                                               int heads, int rowBlockOff) {
    __shared__ __half As[2][GBM][HK + HPAD];
    __shared__ __half Bs[2][GBN][HK + HPAD];
    __shared__ float s_eas[2][GBM];
    __shared__ float s_ead[2][GBM];

    int tid  = threadIdx.x;
    int lane = tid & 31;
    int warp = tid >> 5;
    int wm = warp & 3;
    int wn = warp >> 2;
    int rowBase = (blockIdx.y + rowBlockOff) * GBM;
    int colBase = blockIdx.x * GBN;
    int q  = lane & 3;
    int r0 = lane >> 2;

    int ldRow = tid >> 2;
    int ldCol = (tid & 3) * 8;

    int nIter = K / HK;
    float acc[2][8][4] = {};

    {
        #pragma unroll
        for (int i = 0; i < 2; i++) {
            int row = ldRow + 64 * i;
            int gr = rowBase + row;
            const __half* src = (gr < M) ? &A[(long long)gr * K + ldCol] : A;
            cp16(&As[0][row][ldCol], src, (gr < M) ? 16 : 0);
            cp16(&Bs[0][row][ldCol], &Bt[(long long)(colBase + row) * K + ldCol], 16);
        }
        cp_commit();
    }

    for (int it = 0; it < nIter; it++) {
        int cur = it & 1;
        cp_wait<0>();
        __syncthreads();

        if (it + 1 < nIter) {
            int k0 = (it + 1) * HK;
            int st = cur ^ 1;
            #pragma unroll
            for (int i = 0; i < 2; i++) {
                int row = ldRow + 64 * i;
                int gr = rowBase + row;
                const __half* src = (gr < M) ? &A[(long long)gr * K + k0 + ldCol] : A;
                cp16(&As[st][row][ldCol], src, (gr < M) ? 16 : 0);
                cp16(&Bs[st][row][ldCol], &Bt[(long long)(colBase + row) * K + k0 + ldCol], 16);
            }
            cp_commit();
        }

        #pragma unroll
        for (int kk = 0; kk < 2; kk++) {
            int kb = kk * 16;
            unsigned a[2][4], b[8][2];
            #pragma unroll
            for (int mf = 0; mf < 2; mf++) {
                int mrow = wm * 32 + mf * 16 + r0;
                a[mf][0] = *(const unsigned*)&As[cur][mrow    ][kb + 2*q    ];
                a[mf][1] = *(const unsigned*)&As[cur][mrow + 8][kb + 2*q    ];
                a[mf][2] = *(const unsigned*)&As[cur][mrow    ][kb + 2*q + 8];
                a[mf][3] = *(const unsigned*)&As[cur][mrow + 8][kb + 2*q + 8];
            }
            #pragma unroll
            for (int nf = 0; nf < 8; nf++) {
                int ncol = wn * 64 + nf * 8 + r0;
                b[nf][0] = *(const unsigned*)&Bs[cur][ncol][kb + 2*q    ];
                b[nf][1] = *(const unsigned*)&Bs[cur][ncol][kb + 2*q + 8];
            }
            #pragma unroll
            for (int mf = 0; mf < 2; mf++)
                #pragma unroll
                for (int nf = 0; nf < 8; nf++)
                    mma_f16(acc[mf][nf], a[mf][0], a[mf][1], a[mf][2], a[mf][3],
                            b[nf][0], b[nf][1]);
        }
        __syncthreads();
    }

    int hd = colBase / HID;
    float attSv[16], attDv[16];
    #pragma unroll
    for (int nf = 0; nf < 8; nf++) {
        int gc = colBase + wn * 64 + nf * 8 + 2 * q;
        attSv[nf*2]   = attS[gc];   attSv[nf*2+1] = attS[gc+1];
        attDv[nf*2]   = attD[gc];   attDv[nf*2+1] = attD[gc+1];
    }
    #pragma unroll
    for (int mf = 0; mf < 2; mf++) {
        int rT = wm * 32 + mf * 16 + r0;
        float psT = 0.f, pdT = 0.f, psB = 0.f, pdB = 0.f;
        #pragma unroll
        for (int nf = 0; nf < 8; nf++) {
            psT += acc[mf][nf][0]*attSv[nf*2] + acc[mf][nf][1]*attSv[nf*2+1];
            pdT += acc[mf][nf][0]*attDv[nf*2] + acc[mf][nf][1]*attDv[nf*2+1];
            psB += acc[mf][nf][2]*attSv[nf*2] + acc[mf][nf][3]*attSv[nf*2+1];
            pdB += acc[mf][nf][2]*attDv[nf*2] + acc[mf][nf][3]*attDv[nf*2+1];
        }
        #pragma unroll
        for (int o = 1; o < 4; o <<= 1) {
            psT += __shfl_xor_sync(0xffffffffu, psT, o);
            pdT += __shfl_xor_sync(0xffffffffu, pdT, o);
            psB += __shfl_xor_sync(0xffffffffu, psB, o);
            pdB += __shfl_xor_sync(0xffffffffu, pdB, o);
        }
        if (q == 0) {
            s_eas[wn][rT]     = psT;  s_ead[wn][rT]     = pdT;
            s_eas[wn][rT + 8] = psB;  s_ead[wn][rT + 8] = pdB;
        }
        #pragma unroll
        for (int nf = 0; nf < 8; nf++) {
            int gc = colBase + wn * 64 + nf * 8 + 2 * q;
            int gr0 = rowBase + rT;
            if (gr0 < M)
                *(__half2*)&Ch[(long long)gr0 * N + gc] =
                    __floats2half2_rn(acc[mf][nf][0], acc[mf][nf][1]);
            if (gr0 + 8 < M)
                *(__half2*)&Ch[(long long)(gr0 + 8) * N + gc] =
                    __floats2half2_rn(acc[mf][nf][2], acc[mf][nf][3]);
        }
    }
    __syncthreads();
    if (tid < GBM) {
        int gr = rowBase + tid;
        if (gr < M) {
            asOut[gr * heads + hd] = s_eas[0][tid] + s_eas[1][tid];
            adOut[gr * heads + hd] = s_ead[0][tid] + s_ead[1][tid];
        }
    }
}

__global__ __launch_bounds__(256) void gemm1_kernel(const float* __restrict__ as1,
                                                    const float* __restrict__ ad1) {
    f16_gemm_fused(g_xh, g_w1t, g_h1h, NN, F1, IN_CH, as1, ad1, g_as1, g_ad1,
                   HEADS, 0);
}

__global__ __launch_bounds__(256) void gemm2_kernel(const float* __restrict__ as2,
                                                    const float* __restrict__ ad2,
                                                    int rowBlockOff) {
    f16_gemm_fused(g_h1bh, g_w2t, g_h2h, NN, HID, F1, as2, ad2, g_as2, g_ad2,
                   1, rowBlockOff);
}

// ------------------------- layer-1 aggregation: single pass, vectorized ------
__global__ __launch_bounds__(128) void agg1_kernel(const float* __restrict__ b1,
                                                   int nodeOff) {
    int n = blockIdx.x + nodeOff, t = threadIdx.x;
    int beg = g_rowstart[n], end = g_rowstart[n + 1];
    int head = t >> 5;

    float4 adst = *(const float4*)&g_ad1[n * HEADS];

    __shared__ float4 s_w[32];
    __shared__ int    ssrc[32];
    __shared__ float  s_finv[HEADS];

    float acc0 = 0.f, acc1 = 0.f, acc2 = 0.f, acc3 = 0.f;
    float4 dsum = make_float4(0.f, 0.f, 0.f, 0.f);

    for (int base = beg; base < end; base += 32) {
        int cnt = min(32, end - base);
        __syncthreads();
        if (t < cnt) {
            int s = g_csrsrc[base + t];
            ssrc[t] = s;
            float4 a = *(const float4*)&g_as1[s * HEADS];
            float4 w;
            w.x = __expf(lrelu(a.x + adst.x));
            w.y = __expf(lrelu(a.y + adst.y));
            w.z = __expf(lrelu(a.z + adst.z));
            w.w = __expf(lrelu(a.w + adst.w));
            s_w[t] = w;
            dsum.x += w.x; dsum.y += w.y; dsum.z += w.z; dsum.w += w.w;
        }
        __syncthreads();
        for (int qq = 0; qq < cnt; qq++) {
            int s = ssrc[qq];
            float wq = ((const float*)&s_w[qq])[head];
            uint2 hv = *(const uint2*)&g_h1h[(long long)s * F1 + 4 * t];
            float2 f01 = __half22float2(*(__half2*)&hv.x);
            float2 f23 = __half22float2(*(__half2*)&hv.y);
            acc0 += wq * f01.x; acc1 += wq * f01.y;
            acc2 += wq * f23.x; acc3 += wq * f23.y;
        }
    }
    dsum.x = warpSum(dsum.x); dsum.y = warpSum(dsum.y);
    dsum.z = warpSum(dsum.z); dsum.w = warpSum(dsum.w);
    if (t == 0) {
        s_finv[0] = 1.f / dsum.x; s_finv[1] = 1.f / dsum.y;
        s_finv[2] = 1.f / dsum.z; s_finv[3] = 1.f / dsum.w;
    }
    __syncthreads();
    float fin = s_finv[head];
    float4 bv = *(const float4*)&b1[4 * t];
    __half2 h01 = __floats2half2_rn(fmaxf(acc0 * fin + bv.x, 0.f),
                                    fmaxf(acc1 * fin + bv.y, 0.f));
    __half2 h23 = __floats2half2_rn(fmaxf(acc2 * fin + bv.z, 0.f),
                                    fmaxf(acc3 * fin + bv.w, 0.f));
    *(uint2*)&g_h1bh[(long long)n * F1 + 4 * t] =
        make_uint2(*(unsigned*)&h01, *(unsigned*)&h23);
}

// ------------------------- layer-2 aggregation: single pass + fused pool ------
__global__ __launch_bounds__(128) void agg2_kernel(const float* __restrict__ b2,
                                                   const void* __restrict__ batch) {
    int n = blockIdx.x, t = threadIdx.x;
    int beg = g_rowstart[n], end = g_rowstart[n + 1];
    float adst = g_ad2[n];
    int grp = t >> 6;
    int c   = t & 63;

    __shared__ float s_w[64];
    __shared__ int   ssrc[64];
    __shared__ float s_accB[HID];
    __shared__ float wr2[2];

    float2 acc = make_float2(0.f, 0.f);
    float dsum = 0.f;

    for (int base = beg; base < end; base += 64) {
        int cnt = min(64, end - base);
        __syncthreads();
        if (t < cnt) {
            int s = g_csrsrc[base + t];
            ssrc[t] = s;
            float w = __expf(lrelu(g_as2[s] + adst));
            s_w[t] = w;
            dsum += w;
        }
        __syncthreads();
        for (int qq = grp; qq < cnt; qq += 2) {
            int s = ssrc[qq];
            float w = s_w[qq];
            float2 f = __half22float2(*(const __half2*)&g_h2h[(long long)s * HID + 2 * c]);
            acc.x += w * f.x; acc.y += w * f.y;
        }
    }
    dsum = warpSum(dsum);
    if ((t & 31) == 0 && t < 64) wr2[t >> 5] = dsum;
    if (grp == 1) { s_accB[2 * c] = acc.x; s_accB[2 * c + 1] = acc.y; }
    __syncthreads();
    if (grp == 0) {
        float di = 1.f / (wr2[0] + wr2[1]);
        float o0 = (acc.x + s_accB[2 * c])     * di + b2[2 * c];
        float o1 = (acc.y + s_accB[2 * c + 1]) * di + b2[2 * c + 1];
        int g = clampi(idx_at(batch, n), NG);
        atomicAdd(&g_pooled[g * HID + 2 * c],     o0);
        atomicAdd(&g_pooled[g * HID + 2 * c + 1], o1);
        if (t == 0) atomicAdd(&g_gcnt[g], 1.0f);
    }
}

// ------------------------- MLP head -------------------------
__global__ void mlp_kernel(const float* __restrict__ Wm1, const float* __restrict__ bm1,
                           const float* __restrict__ Wm2, const float* __restrict__ bm2,
                           float* __restrict__ out) {
    int g = blockIdx.x, t = threadIdx.x;
    __shared__ float p[HID], z[HID];
    float c = fmaxf(g_gcnt[g], 1.0f);
    p[t] = g_pooled[g * HID + t] / c;
    __syncthreads();
    float a = bm1[t];
    #pragma unroll 8
    for (int k = 0; k < HID; k++) a += p[k] * Wm1[k * HID + t];
    z[t] = a > 0.f ? a : 0.f;
    __syncthreads();
    if (t < OC) {
        float o = bm2[t];
        #pragma unroll 8
        for (int k = 0; k < HID; k++) o += z[k] * Wm2[k * OC + t];
        out[g * OC + t] = o;
    }
}

// ------------------------- launch -------------------------
// DAG (R15 structure — best validated):
//   s0: cvt_w2, CSR chain ............................ eCSR
//   s2: cvt_x, cvt_w1, gemm1 ......................... eGemm1
//   s0 (wait eGemm1):        agg1_lo -> gemm2_lo
//   s2 (wait eCSR):          agg1_hi -> gemm2_hi ..... eG2hi
//   s0 (wait eG2hi):         agg2 -> mlp
// gemm2 row-block b reads only h1b rows in that block, so per-half ordering
// on each stream is sufficient; agg2 gathers arbitrary h2 rows so it joins both.
// Streams/events created fresh per call, never destroyed (graph-capture safe).
extern "C" void kernel_launch(void* const* d_in, const int* in_sizes, int n_in,
                              void* d_out, int out_size) {
    const float* x    = (const float*)d_in[0];
    const void*  ei   = d_in[1];
    const void*  bat  = d_in[2];
    const float* W1   = (const float*)d_in[3];
    const float* as1  = (const float*)d_in[4];
    const float* ad1  = (const float*)d_in[5];
    const float* b1   = (const float*)d_in[6];
    const float* W2   = (const float*)d_in[7];
    const float* as2  = (const float*)d_in[8];
    const float* ad2  = (const float*)d_in[9];
    const float* b2   = (const float*)d_in[10];
    const float* Wm1  = (const float*)d_in[11];
    const float* bm1  = (const float*)d_in[12];
    const float* Wm2  = (const float*)d_in[13];
    const float* bm2  = (const float*)d_in[14];
    float* out = (float*)d_out;

    cudaStream_t s2;
    cudaStreamCreateWithFlags(&s2, cudaStreamNonBlocking);
    cudaEvent_t eFork, eGemm1, eCSR, eG2hi;
    cudaEventCreateWithFlags(&eFork,  cudaEventDisableTiming);
    cudaEventCreateWithFlags(&eGemm1, cudaEventDisableTiming);
    cudaEventCreateWithFlags(&eCSR,   cudaEventDisableTiming);
    cudaEventCreateWithFlags(&eG2hi,  cudaEventDisableTiming);

    // fork
    cudaEventRecord(eFork, 0);
    cudaStreamWaitEvent(s2, eFork, 0);

    // s2: fp16 conversions + gemm1
    cvt_x_kernel <<<(NN * IN_CH / 4 + 255) / 256, 256, 0, s2>>>(x);
    cvt_w1_kernel<<<(F1 * IN_CH + 255) / 256, 256, 0, s2>>>(W1);
    {
        dim3 grid(F1 / GBN, RB_ALL);
        gemm1_kernel<<<grid, 256, 0, s2>>>(as1, ad1);
    }
    cudaEventRecord(eGemm1, s2);

    // s0: W2 convert + CSR build
    cvt_w2_kernel<<<(HID * F1 + 255) / 256, 256>>>(W2);
    zero_kernel<<<(NN + 255) / 256, 256>>>((const int*)ei);   // must cover NN!
    hist_kernel<<<(NET + 255) / 256, 256>>>(ei);
    scan1_kernel<<<SNB, SCH>>>();
    scan3_kernel<<<(NN + 255) / 256, 256>>>();
    scatter_kernel<<<(NET + 255) / 256, 256>>>(ei);
    cudaEventRecord(eCSR, 0);

    // s0: lo half — agg1 then gemm2 (needs gemm1 output + CSR)
    cudaStreamWaitEvent(0, eGemm1, 0);
    agg1_kernel<<<NLO, 128>>>(b1, 0);
    {
        dim3 grid(HID / GBN, RB_LO);
        gemm2_kernel<<<grid, 256>>>(as2, ad2, 0);
    }

    // s2: hi half — agg1 then gemm2 (gemm1 already on s2; wait CSR)
    cudaStreamWaitEvent(s2, eCSR, 0);
    agg1_kernel<<<NN - NLO, 128, 0, s2>>>(b1, NLO);
    {
        dim3 grid(HID / GBN, RB_HI);
        gemm2_kernel<<<grid, 256, 0, s2>>>(as2, ad2, RB_LO);
    }
    cudaEventRecord(eG2hi, s2);

    // join: agg2 needs full g_h2h + g_as2/g_ad2
    cudaStreamWaitEvent(0, eG2hi, 0);
    agg2_kernel<<<NN, 128>>>(b2, bat);

    mlp_kernel<<<NG, HID>>>(Wm1, bm1, Wm2, bm2, out);
}